// round 3
// baseline (speedup 1.0000x reference)
#include <cuda_runtime.h>
#include <cstdint>
#include <cstddef>

// B=8, N=1024, C=1024, H=16, D=64, scale = 0.125
#define BB 8
#define NN 1024
#define CC 1024
#define HH 16
#define DD 64
#define SCALE 0.125f

#define ROWS 32          // query rows per block in fused attention
#define PSTRIDE 1028     // probs row stride (pad 4 -> conflict-free frags)

__device__ float g_qkv[(size_t)BB * NN * 3 * CC];   // (B,N,3,H,D)
__device__ float g_ctx[(size_t)BB * NN * CC];       // (B,N,H*D)

__device__ __forceinline__ unsigned f2tf(float f) {
    unsigned u;
    asm("cvt.rna.tf32.f32 %0, %1;" : "=r"(u) : "f"(f));
    return u;
}

__device__ __forceinline__ void mma_tf32(float c[4],
    unsigned a0, unsigned a1, unsigned a2, unsigned a3,
    unsigned b0, unsigned b1)
{
    asm volatile(
        "mma.sync.aligned.m16n8k8.row.col.f32.tf32.tf32.f32 "
        "{%0,%1,%2,%3}, {%4,%5,%6,%7}, {%8,%9}, {%0,%1,%2,%3};\n"
        : "+f"(c[0]), "+f"(c[1]), "+f"(c[2]), "+f"(c[3])
        : "r"(a0), "r"(a1), "r"(a2), "r"(a3), "r"(b0), "r"(b1));
}

// ---------------------------------------------------------------------------
// TF32 tensor-core SGEMM + bias: C[M,N] = A[M,K] @ B[K,N] + bias[N]
// 128x128 block tile, BK=16, 256 threads (8 warps, 4x2), warp tile 32x64.
// ---------------------------------------------------------------------------
__global__ __launch_bounds__(256) void sgemm_bias_tc(
    const float* __restrict__ A, const float* __restrict__ Bm,
    const float* __restrict__ bias, float* __restrict__ C,
    int M, int N, int K)
{
    __shared__ unsigned As[16][136];   // [k][m]
    __shared__ unsigned Bs[16][136];   // [k][n]

    const int tid  = threadIdx.x;
    const int brow = blockIdx.y * 128;
    const int bcol = blockIdx.x * 128;
    const int w  = tid >> 5, l = tid & 31;
    const int wr = w >> 1, wc = w & 1;
    const int g  = l >> 2, t = l & 3;

    const int ar  = tid >> 1;
    const int ac4 = (tid & 1) * 2;

    float acc[2][8][4];
#pragma unroll
    for (int i = 0; i < 2; i++)
#pragma unroll
        for (int j = 0; j < 8; j++)
#pragma unroll
            for (int r = 0; r < 4; r++) acc[i][j][r] = 0.0f;

    for (int k0 = 0; k0 < K; k0 += 16) {
#pragma unroll
        for (int j = 0; j < 2; j++) {
            const int c4 = ac4 + j;
            float4 v = *reinterpret_cast<const float4*>(
                &A[(size_t)(brow + ar) * K + k0 + c4 * 4]);
            As[c4 * 4 + 0][ar] = f2tf(v.x);
            As[c4 * 4 + 1][ar] = f2tf(v.y);
            As[c4 * 4 + 2][ar] = f2tf(v.z);
            As[c4 * 4 + 3][ar] = f2tf(v.w);
        }
#pragma unroll
        for (int j = 0; j < 2; j++) {
            const int idx = tid * 2 + j;
            const int r = idx >> 5, c4 = idx & 31;
            float4 v = *reinterpret_cast<const float4*>(
                &Bm[(size_t)(k0 + r) * N + bcol + c4 * 4]);
            uint4 u = {f2tf(v.x), f2tf(v.y), f2tf(v.z), f2tf(v.w)};
            *reinterpret_cast<uint4*>(&Bs[r][c4 * 4]) = u;
        }
        __syncthreads();

#pragma unroll
        for (int kk = 0; kk < 16; kk += 8) {
            unsigned a[2][4], b[8][2];
#pragma unroll
            for (int i = 0; i < 2; i++) {
                const int m0 = wr * 32 + i * 16;
                a[i][0] = As[kk + t][m0 + g];
                a[i][1] = As[kk + t][m0 + g + 8];
                a[i][2] = As[kk + t + 4][m0 + g];
                a[i][3] = As[kk + t + 4][m0 + g + 8];
            }
#pragma unroll
            for (int j = 0; j < 8; j++) {
                const int n0 = wc * 64 + j * 8;
                b[j][0] = Bs[kk + t][n0 + g];
                b[j][1] = Bs[kk + t + 4][n0 + g];
            }
#pragma unroll
            for (int i = 0; i < 2; i++)
#pragma unroll
                for (int j = 0; j < 8; j++)
                    mma_tf32(acc[i][j], a[i][0], a[i][1], a[i][2], a[i][3],
                             b[j][0], b[j][1]);
        }
        __syncthreads();
    }

#pragma unroll
    for (int j = 0; j < 8; j++) {
        const int col = bcol + wc * 64 + j * 8 + t * 2;
        const float b0 = bias[col], b1 = bias[col + 1];
#pragma unroll
        for (int i = 0; i < 2; i++) {
            const int r0 = brow + wr * 32 + i * 16;
            float2 o0 = {acc[i][j][0] + b0, acc[i][j][1] + b1};
            float2 o1 = {acc[i][j][2] + b0, acc[i][j][3] + b1};
            *reinterpret_cast<float2*>(&C[(size_t)(r0 + g) * N + col]) = o0;
            *reinterpret_cast<float2*>(&C[(size_t)(r0 + g + 8) * N + col]) = o1;
        }
    }
}

// ---------------------------------------------------------------------------
// Fused attention: QK^T -> softmax -> (write attn) -> PV -> ctx
// One block: 32 query rows x 1024 keys for one (b,h). 512 threads, 16 warps.
// Dynamic smem: probs[32][1028] fp32 | Qs[32][68] tf32 | KV[128][72] tf32
// ---------------------------------------------------------------------------
__global__ __launch_bounds__(512) void fused_attn(
    const float* __restrict__ qkv, float* __restrict__ attn,
    float* __restrict__ ctx)
{
    extern __shared__ float sm[];
    float* probs = sm;                                   // [32][1028]
    unsigned* QsU = (unsigned*)(sm + ROWS * PSTRIDE);    // [32][68]
    unsigned* KVU = QsU + ROWS * 68;                     // K:[128][68] V:[128][72]

    const int bh = blockIdx.y;
    const int b  = bh >> 4;
    const int h  = bh & 15;
    const int n0 = blockIdx.x * ROWS;

    const int tid = threadIdx.x;
    const int w = tid >> 5, l = tid & 31;
    const int g = l >> 2, t = l & 3;

    const float* qbase = qkv + (size_t)b * NN * 3 * CC + h * DD;   // s=0
    const float* kbase = qbase + CC;                                // s=1
    const float* vbase = qbase + 2 * CC;                            // s=2

    // ---- load Q tile (32 x 64), pre-scaled, tf32 ----
    {
        const int r  = tid >> 4;
        const int c4 = tid & 15;
        float4 v = *reinterpret_cast<const float4*>(
            qbase + (size_t)(n0 + r) * (3 * CC) + c4 * 4);
        uint4 u = {f2tf(v.x * SCALE), f2tf(v.y * SCALE),
                   f2tf(v.z * SCALE), f2tf(v.w * SCALE)};
        *reinterpret_cast<uint4*>(&QsU[r * 68 + c4 * 4]) = u;
    }

    // ---- Phase 1: scores = Q K^T into probs smem ----
    const int wr = w >> 3;         // 0..1 : 16-row slab
    const int wc = w & 7;          // 0..7 : 16-col slab (within 128-key tile)
    const int r0 = wr * 16;
    const int c0 = wc * 16;

    for (int m0 = 0; m0 < NN; m0 += 128) {
        // K tile 128x64 -> KVU[m][d], stride 68
#pragma unroll
        for (int j = 0; j < 4; j++) {
            const int idx = tid + 512 * j;
            const int m = idx >> 4, c4 = idx & 15;
            float4 v = *reinterpret_cast<const float4*>(
                kbase + (size_t)(m0 + m) * (3 * CC) + c4 * 4);
            uint4 u = {f2tf(v.x), f2tf(v.y), f2tf(v.z), f2tf(v.w)};
            *reinterpret_cast<uint4*>(&KVU[m * 68 + c4 * 4]) = u;
        }
        __syncthreads();

        float acc0[4] = {0, 0, 0, 0}, acc1[4] = {0, 0, 0, 0};
#pragma unroll
        for (int kk = 0; kk < DD; kk += 8) {
            unsigned a0 = QsU[(r0 + g) * 68 + kk + t];
            unsigned a1 = QsU[(r0 + g + 8) * 68 + kk + t];
            unsigned a2 = QsU[(r0 + g) * 68 + kk + t + 4];
            unsigned a3 = QsU[(r0 + g + 8) * 68 + kk + t + 4];
            unsigned b0 = KVU[(c0 + g) * 68 + kk + t];
            unsigned b1 = KVU[(c0 + g) * 68 + kk + t + 4];
            unsigned b2 = KVU[(c0 + 8 + g) * 68 + kk + t];
            unsigned b3 = KVU[(c0 + 8 + g) * 68 + kk + t + 4];
            mma_tf32(acc0, a0, a1, a2, a3, b0, b1);
            mma_tf32(acc1, a0, a1, a2, a3, b2, b3);
        }
        const int cb = m0 + c0;
        probs[(r0 + g) * PSTRIDE + cb + 2 * t]         = acc0[0];
        probs[(r0 + g) * PSTRIDE + cb + 2 * t + 1]     = acc0[1];
        probs[(r0 + g + 8) * PSTRIDE + cb + 2 * t]     = acc0[2];
        probs[(r0 + g + 8) * PSTRIDE + cb + 2 * t + 1] = acc0[3];
        probs[(r0 + g) * PSTRIDE + cb + 8 + 2 * t]         = acc1[0];
        probs[(r0 + g) * PSTRIDE + cb + 8 + 2 * t + 1]     = acc1[1];
        probs[(r0 + g + 8) * PSTRIDE + cb + 8 + 2 * t]     = acc1[2];
        probs[(r0 + g + 8) * PSTRIDE + cb + 8 + 2 * t + 1] = acc1[3];
        __syncthreads();
    }

    // ---- Phase 2: softmax over each row; write normalized probs to gmem ----
    {
        float* arow = attn + ((size_t)bh * NN + n0) * NN;
#pragma unroll
        for (int rr = 0; rr < 2; rr++) {
            const int r = 2 * w + rr;
            float* pr = probs + r * PSTRIDE;
            float4 vv[8];
            float mx = -3.402823466e+38f;
#pragma unroll
            for (int i = 0; i < 8; i++) {
                vv[i] = *reinterpret_cast<float4*>(&pr[i * 128 + 4 * l]);
                mx = fmaxf(mx, fmaxf(fmaxf(vv[i].x, vv[i].y),
                                     fmaxf(vv[i].z, vv[i].w)));
            }
#pragma unroll
            for (int o = 16; o; o >>= 1)
                mx = fmaxf(mx, __shfl_xor_sync(0xffffffffu, mx, o));
            float s = 0.0f;
#pragma unroll
            for (int i = 0; i < 8; i++) {
                vv[i].x = __expf(vv[i].x - mx);
                vv[i].y = __expf(vv[i].y - mx);
                vv[i].z = __expf(vv[i].z - mx);
                vv[i].w = __expf(vv[i].w - mx);
                s += vv[i].x + vv[i].y + vv[i].z + vv[i].w;
            }
#pragma unroll
            for (int o = 16; o; o >>= 1)
                s += __shfl_xor_sync(0xffffffffu, s, o);
            const float inv = 1.0f / s;
#pragma unroll
            for (int i = 0; i < 8; i++) {
                vv[i].x *= inv; vv[i].y *= inv;
                vv[i].z *= inv; vv[i].w *= inv;
                *reinterpret_cast<float4*>(&pr[i * 128 + 4 * l]) = vv[i];
                *reinterpret_cast<float4*>(
                    &arow[(size_t)r * NN + i * 128 + 4 * l]) = vv[i];
            }
        }
    }

    // ---- Phase 3: ctx = probs @ V ----
    // warp (wr, wc): rows wr*16, cols wc*8 of the 32x64 output
    float oacc[4] = {0, 0, 0, 0};
    for (int v0 = 0; v0 < NN; v0 += 128) {
        // V tile 128x64 -> KVU[m][d], stride 72
#pragma unroll
        for (int j = 0; j < 4; j++) {
            const int idx = tid + 512 * j;
            const int m = idx >> 4, c4 = idx & 15;
            float4 v = *reinterpret_cast<const float4*>(
                vbase + (size_t)(v0 + m) * (3 * CC) + c4 * 4);
            uint4 u = {f2tf(v.x), f2tf(v.y), f2tf(v.z), f2tf(v.w)};
            *reinterpret_cast<uint4*>(&KVU[m * 72 + c4 * 4]) = u;
        }
        __syncthreads();

#pragma unroll
        for (int kk = 0; kk < 128; kk += 8) {
            unsigned a0 = f2tf(probs[(r0 + g) * PSTRIDE + v0 + kk + t]);
            unsigned a1 = f2tf(probs[(r0 + g + 8) * PSTRIDE + v0 + kk + t]);
            unsigned a2 = f2tf(probs[(r0 + g) * PSTRIDE + v0 + kk + t + 4]);
            unsigned a3 = f2tf(probs[(r0 + g + 8) * PSTRIDE + v0 + kk + t + 4]);
            unsigned b0 = KVU[(kk + t) * 72 + wc * 8 + g];
            unsigned b1 = KVU[(kk + t + 4) * 72 + wc * 8 + g];
            mma_tf32(oacc, a0, a1, a2, a3, b0, b1);
        }
        __syncthreads();
    }

    {
        const int row = n0 + r0 + g;
        const int col = h * DD + wc * 8 + 2 * t;
        float2 o0 = {oacc[0], oacc[1]};
        float2 o1 = {oacc[2], oacc[3]};
        *reinterpret_cast<float2*>(&ctx[((size_t)b * NN + row) * CC + col]) = o0;
        *reinterpret_cast<float2*>(&ctx[((size_t)b * NN + row + 8) * CC + col]) = o1;
    }
}

// ---------------------------------------------------------------------------
extern "C" void kernel_launch(void* const* d_in, const int* in_sizes, int n_in,
                              void* d_out, int out_size)
{
    (void)in_sizes; (void)n_in; (void)out_size;
    const float* x      = (const float*)d_in[0];
    const float* w_qkv  = (const float*)d_in[1];
    const float* b_qkv  = (const float*)d_in[2];
    const float* w_proj = (const float*)d_in[3];
    const float* b_proj = (const float*)d_in[4];

    float* out  = (float*)d_out;
    float* attn = out + (size_t)BB * NN * CC;

    float* qkvp = nullptr;
    float* ctxp = nullptr;
    cudaGetSymbolAddress((void**)&qkvp, g_qkv);
    cudaGetSymbolAddress((void**)&ctxp, g_ctx);

    const int smem_bytes = (ROWS * PSTRIDE + ROWS * 68 + 128 * 72) * 4;
    static bool attr_set = false;
    if (!attr_set) {
        cudaFuncSetAttribute(fused_attn,
            cudaFuncAttributeMaxDynamicSharedMemorySize, smem_bytes);
        attr_set = true;
    }

    // 1) QKV projection (tf32 TC)
    sgemm_bias_tc<<<dim3(3 * CC / 128, BB * NN / 128), 256>>>(
        x, w_qkv, b_qkv, qkvp, BB * NN, 3 * CC, CC);

    // 2) Fused QK^T + softmax + attn-write + PV
    fused_attn<<<dim3(NN / ROWS, BB * HH), 512, smem_bytes>>>(
        qkvp, attn, ctxp);

    // 3) Output projection (tf32 TC)
    sgemm_bias_tc<<<dim3(CC / 128, BB * NN / 128), 256>>>(
        ctxp, w_proj, b_proj, out, BB * NN, CC, CC);
}

// round 4
// speedup vs baseline: 1.1926x; 1.1926x over previous
#include <cuda_runtime.h>
#include <cstdint>
#include <cstddef>

// B=8, N=1024, C=1024, H=16, D=64, scale = 0.125
#define BB 8
#define NN 1024
#define CC 1024
#define HH 16
#define DD 64
#define SCALE 0.125f

__device__ float g_qkv[(size_t)BB * NN * 3 * CC];   // (B,N,3,H,D)
__device__ float g_ctx[(size_t)BB * NN * CC];       // (B,N,H*D)

__device__ __forceinline__ unsigned f2tf(float f) {
    unsigned u;
    asm("cvt.rna.tf32.f32 %0, %1;" : "=r"(u) : "f"(f));
    return u;
}

__device__ __forceinline__ void mma_tf32(float c[4],
    unsigned a0, unsigned a1, unsigned a2, unsigned a3,
    unsigned b0, unsigned b1)
{
    asm volatile(
        "mma.sync.aligned.m16n8k8.row.col.f32.tf32.tf32.f32 "
        "{%0,%1,%2,%3}, {%4,%5,%6,%7}, {%8,%9}, {%0,%1,%2,%3};\n"
        : "+f"(c[0]), "+f"(c[1]), "+f"(c[2]), "+f"(c[3])
        : "r"(a0), "r"(a1), "r"(a2), "r"(a3), "r"(b0), "r"(b1));
}

// ---------------------------------------------------------------------------
// TF32 TC SGEMM + bias, software-pipelined (register prefetch of next tile).
// 128x128 block tile, BK=16, 256 threads (8 warps, 4x2), warp tile 32x64.
// ---------------------------------------------------------------------------
__global__ __launch_bounds__(256) void sgemm_bias_tc(
    const float* __restrict__ A, const float* __restrict__ Bm,
    const float* __restrict__ bias, float* __restrict__ C,
    int M, int N, int K)
{
    __shared__ unsigned As[16][136];   // [k][m]
    __shared__ unsigned Bs[16][136];   // [k][n]

    const int tid  = threadIdx.x;
    const int brow = blockIdx.y * 128;
    const int bcol = blockIdx.x * 128;
    const int w  = tid >> 5, l = tid & 31;
    const int wr = w >> 1, wc = w & 1;
    const int g  = l >> 2, t = l & 3;

    const int ar  = tid >> 1;        // A fill row 0..127
    const int ac4 = (tid & 1) * 2;   // A fill float4-col base
    const int br_ = (tid * 2) >> 5;          // B fill rows for j=0 (j=1: +? same formula)
    (void)br_;

    float4 a_r[2], b_r[2];

    auto ldg_tiles = [&](int k0) {
#pragma unroll
        for (int j = 0; j < 2; j++) {
            const int c4 = ac4 + j;
            a_r[j] = *reinterpret_cast<const float4*>(
                &A[(size_t)(brow + ar) * K + k0 + c4 * 4]);
        }
#pragma unroll
        for (int j = 0; j < 2; j++) {
            const int idx = tid * 2 + j;
            const int r = idx >> 5, c4 = idx & 31;
            b_r[j] = *reinterpret_cast<const float4*>(
                &Bm[(size_t)(k0 + r) * N + bcol + c4 * 4]);
        }
    };
    auto sts_tiles = [&]() {
#pragma unroll
        for (int j = 0; j < 2; j++) {
            const int c4 = ac4 + j;
            As[c4 * 4 + 0][ar] = f2tf(a_r[j].x);
            As[c4 * 4 + 1][ar] = f2tf(a_r[j].y);
            As[c4 * 4 + 2][ar] = f2tf(a_r[j].z);
            As[c4 * 4 + 3][ar] = f2tf(a_r[j].w);
        }
#pragma unroll
        for (int j = 0; j < 2; j++) {
            const int idx = tid * 2 + j;
            const int r = idx >> 5, c4 = idx & 31;
            uint4 u = {f2tf(b_r[j].x), f2tf(b_r[j].y),
                       f2tf(b_r[j].z), f2tf(b_r[j].w)};
            *reinterpret_cast<uint4*>(&Bs[r][c4 * 4]) = u;
        }
    };

    float acc[2][8][4];
#pragma unroll
    for (int i = 0; i < 2; i++)
#pragma unroll
        for (int j = 0; j < 8; j++)
#pragma unroll
            for (int r = 0; r < 4; r++) acc[i][j][r] = 0.0f;

    ldg_tiles(0);
    for (int k0 = 0; k0 < K; k0 += 16) {
        sts_tiles();
        __syncthreads();
        if (k0 + 16 < K) ldg_tiles(k0 + 16);

#pragma unroll
        for (int kk = 0; kk < 16; kk += 8) {
            unsigned a[2][4], b[8][2];
#pragma unroll
            for (int i = 0; i < 2; i++) {
                const int m0 = wr * 32 + i * 16;
                a[i][0] = As[kk + t][m0 + g];
                a[i][1] = As[kk + t][m0 + g + 8];
                a[i][2] = As[kk + t + 4][m0 + g];
                a[i][3] = As[kk + t + 4][m0 + g + 8];
            }
#pragma unroll
            for (int j = 0; j < 8; j++) {
                const int n0 = wc * 64 + j * 8;
                b[j][0] = Bs[kk + t][n0 + g];
                b[j][1] = Bs[kk + t + 4][n0 + g];
            }
#pragma unroll
            for (int i = 0; i < 2; i++)
#pragma unroll
                for (int j = 0; j < 8; j++)
                    mma_tf32(acc[i][j], a[i][0], a[i][1], a[i][2], a[i][3],
                             b[j][0], b[j][1]);
        }
        __syncthreads();
    }

#pragma unroll
    for (int j = 0; j < 8; j++) {
        const int col = bcol + wc * 64 + j * 8 + t * 2;
        const float b0 = bias[col], b1 = bias[col + 1];
#pragma unroll
        for (int i = 0; i < 2; i++) {
            const int r0 = brow + wr * 32 + i * 16;
            float2 o0 = {acc[i][j][0] + b0, acc[i][j][1] + b1};
            float2 o1 = {acc[i][j][2] + b0, acc[i][j][3] + b1};
            *reinterpret_cast<float2*>(&C[(size_t)(r0 + g) * N + col]) = o0;
            *reinterpret_cast<float2*>(&C[(size_t)(r0 + g + 8) * N + col]) = o1;
        }
    }
}

// ---------------------------------------------------------------------------
// QK^T scores (tf32 TC, pipelined): attn_raw[bh,n,m] = (SCALE*q[n,:]) . k[m,:]
// 128x128 tile, K=64 (BK=16 x 4 iters).
// ---------------------------------------------------------------------------
__global__ __launch_bounds__(256) void qk_scores_tc(
    const float* __restrict__ qkv, float* __restrict__ attn)
{
    __shared__ unsigned As[16][136];   // [d][n]  (Q, pre-scaled)
    __shared__ unsigned Bs[16][136];   // [d][m]  (K)

    const int bh = blockIdx.z;
    const int b  = bh >> 4;
    const int h  = bh & 15;
    const int n0 = blockIdx.y * 128;
    const int m0 = blockIdx.x * 128;

    const float* qbase = qkv + (size_t)b * NN * 3 * CC + h * DD;
    const float* kbase = qbase + CC;

    const int tid = threadIdx.x;
    const int w  = tid >> 5, l = tid & 31;
    const int wr = w >> 1, wc = w & 1;
    const int g  = l >> 2, t = l & 3;
    const int ar  = tid >> 1;
    const int ac4 = (tid & 1) * 2;

    float4 q_r[2], k_r[2];
    auto ldg_tiles = [&](int k0) {
#pragma unroll
        for (int j = 0; j < 2; j++) {
            const int c4 = ac4 + j;
            q_r[j] = *reinterpret_cast<const float4*>(
                qbase + (size_t)(n0 + ar) * (3 * CC) + k0 + c4 * 4);
            k_r[j] = *reinterpret_cast<const float4*>(
                kbase + (size_t)(m0 + ar) * (3 * CC) + k0 + c4 * 4);
        }
    };
    auto sts_tiles = [&]() {
#pragma unroll
        for (int j = 0; j < 2; j++) {
            const int c4 = ac4 + j;
            As[c4 * 4 + 0][ar] = f2tf(q_r[j].x * SCALE);
            As[c4 * 4 + 1][ar] = f2tf(q_r[j].y * SCALE);
            As[c4 * 4 + 2][ar] = f2tf(q_r[j].z * SCALE);
            As[c4 * 4 + 3][ar] = f2tf(q_r[j].w * SCALE);
            Bs[c4 * 4 + 0][ar] = f2tf(k_r[j].x);
            Bs[c4 * 4 + 1][ar] = f2tf(k_r[j].y);
            Bs[c4 * 4 + 2][ar] = f2tf(k_r[j].z);
            Bs[c4 * 4 + 3][ar] = f2tf(k_r[j].w);
        }
    };

    float acc[2][8][4];
#pragma unroll
    for (int i = 0; i < 2; i++)
#pragma unroll
        for (int j = 0; j < 8; j++)
#pragma unroll
            for (int r = 0; r < 4; r++) acc[i][j][r] = 0.0f;

    ldg_tiles(0);
    for (int k0 = 0; k0 < DD; k0 += 16) {
        sts_tiles();
        __syncthreads();
        if (k0 + 16 < DD) ldg_tiles(k0 + 16);

#pragma unroll
        for (int kk = 0; kk < 16; kk += 8) {
            unsigned a[2][4], bfr[8][2];
#pragma unroll
            for (int i = 0; i < 2; i++) {
                const int mm = wr * 32 + i * 16;
                a[i][0] = As[kk + t][mm + g];
                a[i][1] = As[kk + t][mm + g + 8];
                a[i][2] = As[kk + t + 4][mm + g];
                a[i][3] = As[kk + t + 4][mm + g + 8];
            }
#pragma unroll
            for (int j = 0; j < 8; j++) {
                const int nn = wc * 64 + j * 8;
                bfr[j][0] = Bs[kk + t][nn + g];
                bfr[j][1] = Bs[kk + t + 4][nn + g];
            }
#pragma unroll
            for (int i = 0; i < 2; i++)
#pragma unroll
                for (int j = 0; j < 8; j++)
                    mma_tf32(acc[i][j], a[i][0], a[i][1], a[i][2], a[i][3],
                             bfr[j][0], bfr[j][1]);
        }
        __syncthreads();
    }

    float* arow = attn + (size_t)bh * NN * NN;
#pragma unroll
    for (int j = 0; j < 8; j++) {
        const int col = m0 + wc * 64 + j * 8 + t * 2;
#pragma unroll
        for (int i = 0; i < 2; i++) {
            const int r0 = n0 + wr * 32 + i * 16;
            float2 o0 = {acc[i][j][0], acc[i][j][1]};
            float2 o1 = {acc[i][j][2], acc[i][j][3]};
            *reinterpret_cast<float2*>(&arow[(size_t)(r0 + g) * NN + col]) = o0;
            *reinterpret_cast<float2*>(&arow[(size_t)(r0 + g + 8) * NN + col]) = o1;
        }
    }
}

// ---------------------------------------------------------------------------
// Row softmax in place (B*H*N rows of 1024). 256 threads/row.
// ---------------------------------------------------------------------------
__global__ __launch_bounds__(256) void softmax_rows(float* __restrict__ attn)
{
    const size_t row = blockIdx.x;
    float* p = attn + row * NN;
    const int tid = threadIdx.x;

    float4 v = reinterpret_cast<float4*>(p)[tid];
    float m = fmaxf(fmaxf(v.x, v.y), fmaxf(v.z, v.w));

    __shared__ float red[8];
#pragma unroll
    for (int o = 16; o; o >>= 1)
        m = fmaxf(m, __shfl_xor_sync(0xffffffffu, m, o));
    if ((tid & 31) == 0) red[tid >> 5] = m;
    __syncthreads();
    m = red[0];
#pragma unroll
    for (int wv = 1; wv < 8; wv++) m = fmaxf(m, red[wv]);

    v.x = __expf(v.x - m);
    v.y = __expf(v.y - m);
    v.z = __expf(v.z - m);
    v.w = __expf(v.w - m);
    float s = v.x + v.y + v.z + v.w;
#pragma unroll
    for (int o = 16; o; o >>= 1)
        s += __shfl_xor_sync(0xffffffffu, s, o);
    __syncthreads();
    if ((tid & 31) == 0) red[tid >> 5] = s;
    __syncthreads();
    s = red[0];
#pragma unroll
    for (int wv = 1; wv < 8; wv++) s += red[wv];

    const float inv = 1.0f / s;
    v.x *= inv; v.y *= inv; v.z *= inv; v.w *= inv;
    reinterpret_cast<float4*>(p)[tid] = v;
}

// ---------------------------------------------------------------------------
// PV (tf32 TC, pipelined): ctx[b,n,h*64+d] = sum_m attn[bh,n,m] * v[bh,m,d]
// Block: 128 rows x 64 cols (full D), BK=32, warp tile 32x32.
// ---------------------------------------------------------------------------
__global__ __launch_bounds__(256) void av_ctx_tc(
    const float* __restrict__ attn, const float* __restrict__ qkv,
    float* __restrict__ ctx)
{
    __shared__ unsigned As[32][136];   // [m][n]  (P transposed)
    __shared__ unsigned Bs[32][72];    // [m][d]  (V)

    const int bh = blockIdx.y;
    const int b  = bh >> 4;
    const int h  = bh & 15;
    const int n0 = blockIdx.x * 128;

    const float* vbase = qkv + (size_t)b * NN * 3 * CC + 2 * CC + h * DD;
    const float* arow  = attn + ((size_t)bh * NN + n0) * NN;

    const int tid = threadIdx.x;
    const int w  = tid >> 5, l = tid & 31;
    const int wr = w >> 1, wc = w & 1;
    const int g  = l >> 2, t = l & 3;

    float4 p_r[4], v_r[2];
    auto ldg_tiles = [&](int k0) {
#pragma unroll
        for (int j = 0; j < 4; j++) {
            const int idx = tid * 4 + j;
            const int r = idx >> 3, c4 = idx & 7;
            p_r[j] = *reinterpret_cast<const float4*>(
                arow + (size_t)r * NN + k0 + c4 * 4);
        }
#pragma unroll
        for (int j = 0; j < 2; j++) {
            const int idx = tid * 2 + j;
            const int r = idx >> 4, c4 = idx & 15;
            v_r[j] = *reinterpret_cast<const float4*>(
                vbase + (size_t)(k0 + r) * (3 * CC) + c4 * 4);
        }
    };
    auto sts_tiles = [&]() {
#pragma unroll
        for (int j = 0; j < 4; j++) {
            const int idx = tid * 4 + j;
            const int r = idx >> 3, c4 = idx & 7;
            As[c4 * 4 + 0][r] = f2tf(p_r[j].x);
            As[c4 * 4 + 1][r] = f2tf(p_r[j].y);
            As[c4 * 4 + 2][r] = f2tf(p_r[j].z);
            As[c4 * 4 + 3][r] = f2tf(p_r[j].w);
        }
#pragma unroll
        for (int j = 0; j < 2; j++) {
            const int idx = tid * 2 + j;
            const int r = idx >> 4, c4 = idx & 15;
            uint4 u = {f2tf(v_r[j].x), f2tf(v_r[j].y),
                       f2tf(v_r[j].z), f2tf(v_r[j].w)};
            *reinterpret_cast<uint4*>(&Bs[r][c4 * 4]) = u;
        }
    };

    float acc[2][4][4];
#pragma unroll
    for (int i = 0; i < 2; i++)
#pragma unroll
        for (int j = 0; j < 4; j++)
#pragma unroll
            for (int r = 0; r < 4; r++) acc[i][j][r] = 0.0f;

    ldg_tiles(0);
    for (int k0 = 0; k0 < NN; k0 += 32) {
        sts_tiles();
        __syncthreads();
        if (k0 + 32 < NN) ldg_tiles(k0 + 32);

#pragma unroll
        for (int kk = 0; kk < 32; kk += 8) {
            unsigned a[2][4], bfr[4][2];
#pragma unroll
            for (int i = 0; i < 2; i++) {
                const int mm = wr * 32 + i * 16;
                a[i][0] = As[kk + t][mm + g];
                a[i][1] = As[kk + t][mm + g + 8];
                a[i][2] = As[kk + t + 4][mm + g];
                a[i][3] = As[kk + t + 4][mm + g + 8];
            }
#pragma unroll
            for (int j = 0; j < 4; j++) {
                const int dd = wc * 32 + j * 8;
                bfr[j][0] = Bs[kk + t][dd + g];
                bfr[j][1] = Bs[kk + t + 4][dd + g];
            }
#pragma unroll
            for (int i = 0; i < 2; i++)
#pragma unroll
                for (int j = 0; j < 4; j++)
                    mma_tf32(acc[i][j], a[i][0], a[i][1], a[i][2], a[i][3],
                             bfr[j][0], bfr[j][1]);
        }
        __syncthreads();
    }

#pragma unroll
    for (int j = 0; j < 4; j++) {
        const int col = h * DD + wc * 32 + j * 8 + t * 2;
#pragma unroll
        for (int i = 0; i < 2; i++) {
            const int r0 = n0 + wr * 32 + i * 16;
            float2 o0 = {acc[i][j][0], acc[i][j][1]};
            float2 o1 = {acc[i][j][2], acc[i][j][3]};
            *reinterpret_cast<float2*>(
                &ctx[((size_t)b * NN + r0 + g) * CC + col]) = o0;
            *reinterpret_cast<float2*>(
                &ctx[((size_t)b * NN + r0 + g + 8) * CC + col]) = o1;
        }
    }
}

// ---------------------------------------------------------------------------
extern "C" void kernel_launch(void* const* d_in, const int* in_sizes, int n_in,
                              void* d_out, int out_size)
{
    (void)in_sizes; (void)n_in; (void)out_size;
    const float* x      = (const float*)d_in[0];
    const float* w_qkv  = (const float*)d_in[1];
    const float* b_qkv  = (const float*)d_in[2];
    const float* w_proj = (const float*)d_in[3];
    const float* b_proj = (const float*)d_in[4];

    float* out  = (float*)d_out;
    float* attn = out + (size_t)BB * NN * CC;

    float* qkvp = nullptr;
    float* ctxp = nullptr;
    cudaGetSymbolAddress((void**)&qkvp, g_qkv);
    cudaGetSymbolAddress((void**)&ctxp, g_ctx);

    // 1) QKV projection (tf32 TC, pipelined)
    sgemm_bias_tc<<<dim3(3 * CC / 128, BB * NN / 128), 256>>>(
        x, w_qkv, b_qkv, qkvp, BB * NN, 3 * CC, CC);

    // 2) Raw scores (tf32 TC, pipelined)
    qk_scores_tc<<<dim3(NN / 128, NN / 128, BB * HH), 256>>>(qkvp, attn);

    // 3) Softmax in place
    softmax_rows<<<(unsigned)(BB * HH * NN), 256>>>(attn);

    // 4) attn @ V (tf32 TC, pipelined)
    av_ctx_tc<<<dim3(NN / 128, BB * HH), 256>>>(attn, qkvp, ctxp);

    // 5) Output projection (tf32 TC, pipelined)
    sgemm_bias_tc<<<dim3(CC / 128, BB * NN / 128), 256>>>(
        ctxp, w_proj, b_proj, out, BB * NN, CC, CC);
}

// round 5
// speedup vs baseline: 1.2435x; 1.0427x over previous
#include <cuda_runtime.h>
#include <cstdint>
#include <cstddef>

// B=8, N=1024, C=1024, H=16, D=64, scale = 0.125
#define BB 8
#define NN 1024
#define CC 1024
#define HH 16
#define DD 64
#define SCALE 0.125f
#define FROWS 32

__device__ float g_qkv[(size_t)BB * NN * 3 * CC];   // (B,N,3,H,D)
__device__ float g_ctx[(size_t)BB * NN * CC];       // (B,N,H*D)

__device__ __forceinline__ unsigned f2tf(float f) {
    unsigned u;
    asm("cvt.rna.tf32.f32 %0, %1;" : "=r"(u) : "f"(f));
    return u;
}

__device__ __forceinline__ void mma_tf32(float c[4],
    unsigned a0, unsigned a1, unsigned a2, unsigned a3,
    unsigned b0, unsigned b1)
{
    asm volatile(
        "mma.sync.aligned.m16n8k8.row.col.f32.tf32.tf32.f32 "
        "{%0,%1,%2,%3}, {%4,%5,%6,%7}, {%8,%9}, {%0,%1,%2,%3};\n"
        : "+f"(c[0]), "+f"(c[1]), "+f"(c[2]), "+f"(c[3])
        : "r"(a0), "r"(a1), "r"(a2), "r"(a3), "r"(b0), "r"(b1));
}

// ---------------------------------------------------------------------------
// TF32 TC SGEMM + bias, software-pipelined.
// 128x128 block tile, BK=16, 256 threads (8 warps, 4x2), warp tile 32x64.
// ---------------------------------------------------------------------------
__global__ __launch_bounds__(256) void sgemm_bias_tc(
    const float* __restrict__ A, const float* __restrict__ Bm,
    const float* __restrict__ bias, float* __restrict__ C,
    int M, int N, int K)
{
    __shared__ unsigned As[16][136];   // [k][m]
    __shared__ unsigned Bs[16][136];   // [k][n]

    const int tid  = threadIdx.x;
    const int brow = blockIdx.y * 128;
    const int bcol = blockIdx.x * 128;
    const int w  = tid >> 5, l = tid & 31;
    const int wr = w >> 1, wc = w & 1;
    const int g  = l >> 2, t = l & 3;

    const int ar  = tid >> 1;
    const int ac4 = (tid & 1) * 2;

    float4 a_r[2], b_r[2];
    auto ldg_tiles = [&](int k0) {
#pragma unroll
        for (int j = 0; j < 2; j++) {
            const int c4 = ac4 + j;
            a_r[j] = *reinterpret_cast<const float4*>(
                &A[(size_t)(brow + ar) * K + k0 + c4 * 4]);
        }
#pragma unroll
        for (int j = 0; j < 2; j++) {
            const int idx = tid * 2 + j;
            const int r = idx >> 5, c4 = idx & 31;
            b_r[j] = *reinterpret_cast<const float4*>(
                &Bm[(size_t)(k0 + r) * N + bcol + c4 * 4]);
        }
    };
    auto sts_tiles = [&]() {
#pragma unroll
        for (int j = 0; j < 2; j++) {
            const int c4 = ac4 + j;
            As[c4 * 4 + 0][ar] = f2tf(a_r[j].x);
            As[c4 * 4 + 1][ar] = f2tf(a_r[j].y);
            As[c4 * 4 + 2][ar] = f2tf(a_r[j].z);
            As[c4 * 4 + 3][ar] = f2tf(a_r[j].w);
        }
#pragma unroll
        for (int j = 0; j < 2; j++) {
            const int idx = tid * 2 + j;
            const int r = idx >> 5, c4 = idx & 31;
            uint4 u = {f2tf(b_r[j].x), f2tf(b_r[j].y),
                       f2tf(b_r[j].z), f2tf(b_r[j].w)};
            *reinterpret_cast<uint4*>(&Bs[r][c4 * 4]) = u;
        }
    };

    float acc[2][8][4];
#pragma unroll
    for (int i = 0; i < 2; i++)
#pragma unroll
        for (int j = 0; j < 8; j++)
#pragma unroll
            for (int r = 0; r < 4; r++) acc[i][j][r] = 0.0f;

    ldg_tiles(0);
    for (int k0 = 0; k0 < K; k0 += 16) {
        sts_tiles();
        __syncthreads();
        if (k0 + 16 < K) ldg_tiles(k0 + 16);

#pragma unroll
        for (int kk = 0; kk < 16; kk += 8) {
            unsigned a[2][4], b[8][2];
#pragma unroll
            for (int i = 0; i < 2; i++) {
                const int m0 = wr * 32 + i * 16;
                a[i][0] = As[kk + t][m0 + g];
                a[i][1] = As[kk + t][m0 + g + 8];
                a[i][2] = As[kk + t + 4][m0 + g];
                a[i][3] = As[kk + t + 4][m0 + g + 8];
            }
#pragma unroll
            for (int j = 0; j < 8; j++) {
                const int n0 = wc * 64 + j * 8;
                b[j][0] = Bs[kk + t][n0 + g];
                b[j][1] = Bs[kk + t + 4][n0 + g];
            }
#pragma unroll
            for (int i = 0; i < 2; i++)
#pragma unroll
                for (int j = 0; j < 8; j++)
                    mma_tf32(acc[i][j], a[i][0], a[i][1], a[i][2], a[i][3],
                             b[j][0], b[j][1]);
        }
        __syncthreads();
    }

#pragma unroll
    for (int j = 0; j < 8; j++) {
        const int col = bcol + wc * 64 + j * 8 + t * 2;
        const float b0 = bias[col], b1 = bias[col + 1];
#pragma unroll
        for (int i = 0; i < 2; i++) {
            const int r0 = brow + wr * 32 + i * 16;
            float2 o0 = {acc[i][j][0] + b0, acc[i][j][1] + b1};
            float2 o1 = {acc[i][j][2] + b0, acc[i][j][3] + b1};
            *reinterpret_cast<float2*>(&C[(size_t)(r0 + g) * N + col]) = o0;
            *reinterpret_cast<float2*>(&C[(size_t)(r0 + g + 8) * N + col]) = o1;
        }
    }
}

// ---------------------------------------------------------------------------
// Fused QK^T + softmax: writes normalized attn probs exactly once.
// Block: 32 query rows x ALL 1024 keys of one (b,h). 512 threads, 16 warps.
// Scores live in registers (acc[8][2][4] per thread). K streamed via smem.
// Warp (wr = w>>3, wc = w&7): rows wr*16..+16, cols wc*16..+16 of each
// 128-key chunk.
// ---------------------------------------------------------------------------
__global__ __launch_bounds__(512) void qk_softmax_fused(
    const float* __restrict__ qkv, float* __restrict__ attn)
{
    __shared__ unsigned QsU[FROWS * 68];   // [row][d]
    __shared__ unsigned KU[128 * 68];      // [m][d]
    __shared__ float redM[32 * 9];
    __shared__ float redS[32 * 9];

    const int bh = blockIdx.y;
    const int b  = bh >> 4;
    const int h  = bh & 15;
    const int n0 = blockIdx.x * FROWS;

    const int tid = threadIdx.x;
    const int w = tid >> 5, l = tid & 31;
    const int g = l >> 2, t = l & 3;
    const int wr = w >> 3, wc = w & 7;

    const float* qbase = qkv + (size_t)b * NN * 3 * CC + h * DD;   // s=0
    const float* kbase = qbase + CC;                                // s=1

    // ---- load Q tile (32 x 64), pre-scaled, tf32 ----
    {
        const int r  = tid >> 4;
        const int c4 = tid & 15;
        float4 v = *reinterpret_cast<const float4*>(
            qbase + (size_t)(n0 + r) * (3 * CC) + c4 * 4);
        uint4 u = {f2tf(v.x * SCALE), f2tf(v.y * SCALE),
                   f2tf(v.z * SCALE), f2tf(v.w * SCALE)};
        *reinterpret_cast<uint4*>(&QsU[r * 68 + c4 * 4]) = u;
    }

    // K tile prefetch (128 keys x 64 d per chunk; 4 float4 per thread)
    float4 kpre[4];
    auto ldg_k = [&](int m0) {
#pragma unroll
        for (int j = 0; j < 4; j++) {
            const int idx = tid + 512 * j;
            const int m = idx >> 4, c4 = idx & 15;
            kpre[j] = *reinterpret_cast<const float4*>(
                kbase + (size_t)(m0 + m) * (3 * CC) + c4 * 4);
        }
    };
    auto sts_k = [&]() {
#pragma unroll
        for (int j = 0; j < 4; j++) {
            const int idx = tid + 512 * j;
            const int m = idx >> 4, c4 = idx & 15;
            uint4 u = {f2tf(kpre[j].x), f2tf(kpre[j].y),
                       f2tf(kpre[j].z), f2tf(kpre[j].w)};
            *reinterpret_cast<uint4*>(&KU[m * 68 + c4 * 4]) = u;
        }
    };

    float acc[8][2][4];
#pragma unroll
    for (int c = 0; c < 8; c++)
#pragma unroll
        for (int jn = 0; jn < 2; jn++)
#pragma unroll
            for (int r = 0; r < 4; r++) acc[c][jn][r] = 0.0f;

    const int row0 = wr * 16 + g;      // local row in 0..31
    const int row1 = row0 + 8;

    ldg_k(0);
    __syncthreads();                   // Q tile visible
#pragma unroll
    for (int c = 0; c < 8; c++) {
        sts_k();
        __syncthreads();
        if (c < 7) ldg_k((c + 1) * 128);

#pragma unroll
        for (int ks = 0; ks < 8; ks++) {
            const int kk = ks * 8;
            const unsigned a0 = QsU[(row0)      * 68 + kk + t];
            const unsigned a1 = QsU[(row0 + 8)  * 68 + kk + t];
            const unsigned a2 = QsU[(row0)      * 68 + kk + t + 4];
            const unsigned a3 = QsU[(row0 + 8)  * 68 + kk + t + 4];
#pragma unroll
            for (int jn = 0; jn < 2; jn++) {
                const int m = wc * 16 + jn * 8 + g;
                const unsigned b0 = KU[m * 68 + kk + t];
                const unsigned b1 = KU[m * 68 + kk + t + 4];
                mma_tf32(acc[c][jn], a0, a1, a2, a3, b0, b1);
            }
        }
        __syncthreads();
    }

    // ---- softmax over full 1024-wide rows ----
    float mx0 = -3.402823466e+38f, mx1 = -3.402823466e+38f;
#pragma unroll
    for (int c = 0; c < 8; c++)
#pragma unroll
        for (int jn = 0; jn < 2; jn++) {
            mx0 = fmaxf(mx0, fmaxf(acc[c][jn][0], acc[c][jn][1]));
            mx1 = fmaxf(mx1, fmaxf(acc[c][jn][2], acc[c][jn][3]));
        }
#pragma unroll
    for (int o = 1; o <= 2; o <<= 1) {
        mx0 = fmaxf(mx0, __shfl_xor_sync(0xffffffffu, mx0, o));
        mx1 = fmaxf(mx1, __shfl_xor_sync(0xffffffffu, mx1, o));
    }
    if (t == 0) {
        redM[row0 * 9 + wc] = mx0;
        redM[row1 * 9 + wc] = mx1;
    }
    __syncthreads();
    mx0 = redM[row0 * 9];
    mx1 = redM[row1 * 9];
#pragma unroll
    for (int k = 1; k < 8; k++) {
        mx0 = fmaxf(mx0, redM[row0 * 9 + k]);
        mx1 = fmaxf(mx1, redM[row1 * 9 + k]);
    }

    float s0 = 0.0f, s1 = 0.0f;
#pragma unroll
    for (int c = 0; c < 8; c++)
#pragma unroll
        for (int jn = 0; jn < 2; jn++) {
            acc[c][jn][0] = __expf(acc[c][jn][0] - mx0);
            acc[c][jn][1] = __expf(acc[c][jn][1] - mx0);
            acc[c][jn][2] = __expf(acc[c][jn][2] - mx1);
            acc[c][jn][3] = __expf(acc[c][jn][3] - mx1);
            s0 += acc[c][jn][0] + acc[c][jn][1];
            s1 += acc[c][jn][2] + acc[c][jn][3];
        }
#pragma unroll
    for (int o = 1; o <= 2; o <<= 1) {
        s0 += __shfl_xor_sync(0xffffffffu, s0, o);
        s1 += __shfl_xor_sync(0xffffffffu, s1, o);
    }
    if (t == 0) {
        redS[row0 * 9 + wc] = s0;
        redS[row1 * 9 + wc] = s1;
    }
    __syncthreads();
    s0 = redS[row0 * 9];
    s1 = redS[row1 * 9];
#pragma unroll
    for (int k = 1; k < 8; k++) {
        s0 += redS[row0 * 9 + k];
        s1 += redS[row1 * 9 + k];
    }
    const float inv0 = 1.0f / s0;
    const float inv1 = 1.0f / s1;

    // ---- write normalized probs (single HBM pass) ----
    float* arow0 = attn + ((size_t)bh * NN + n0 + row0) * NN;
    float* arow1 = attn + ((size_t)bh * NN + n0 + row1) * NN;
#pragma unroll
    for (int c = 0; c < 8; c++)
#pragma unroll
        for (int jn = 0; jn < 2; jn++) {
            const int col = c * 128 + wc * 16 + jn * 8 + 2 * t;
            float2 o0 = {acc[c][jn][0] * inv0, acc[c][jn][1] * inv0};
            float2 o1 = {acc[c][jn][2] * inv1, acc[c][jn][3] * inv1};
            *reinterpret_cast<float2*>(&arow0[col]) = o0;
            *reinterpret_cast<float2*>(&arow1[col]) = o1;
        }
}

// ---------------------------------------------------------------------------
// PV (tf32 TC, pipelined): ctx[b,n,h*64+d] = sum_m attn[bh,n,m] * v[bh,m,d]
// Block: 128 rows x 64 cols (full D), BK=32, warp tile 32x32.
// ---------------------------------------------------------------------------
__global__ __launch_bounds__(256) void av_ctx_tc(
    const float* __restrict__ attn, const float* __restrict__ qkv,
    float* __restrict__ ctx)
{
    __shared__ unsigned As[32][136];   // [m][n]  (P transposed)
    __shared__ unsigned Bs[32][72];    // [m][d]  (V)

    const int bh = blockIdx.y;
    const int b  = bh >> 4;
    const int h  = bh & 15;
    const int n0 = blockIdx.x * 128;

    const float* vbase = qkv + (size_t)b * NN * 3 * CC + 2 * CC + h * DD;
    const float* arow  = attn + ((size_t)bh * NN + n0) * NN;

    const int tid = threadIdx.x;
    const int w  = tid >> 5, l = tid & 31;
    const int wr = w >> 1, wc = w & 1;
    const int g  = l >> 2, t = l & 3;

    float4 p_r[4], v_r[2];
    auto ldg_tiles = [&](int k0) {
#pragma unroll
        for (int j = 0; j < 4; j++) {
            const int idx = tid * 4 + j;
            const int r = idx >> 3, c4 = idx & 7;
            p_r[j] = *reinterpret_cast<const float4*>(
                arow + (size_t)r * NN + k0 + c4 * 4);
        }
#pragma unroll
        for (int j = 0; j < 2; j++) {
            const int idx = tid * 2 + j;
            const int r = idx >> 4, c4 = idx & 15;
            v_r[j] = *reinterpret_cast<const float4*>(
                vbase + (size_t)(k0 + r) * (3 * CC) + c4 * 4);
        }
    };
    auto sts_tiles = [&]() {
#pragma unroll
        for (int j = 0; j < 4; j++) {
            const int idx = tid * 4 + j;
            const int r = idx >> 3, c4 = idx & 7;
            As[c4 * 4 + 0][r] = f2tf(p_r[j].x);
            As[c4 * 4 + 1][r] = f2tf(p_r[j].y);
            As[c4 * 4 + 2][r] = f2tf(p_r[j].z);
            As[c4 * 4 + 3][r] = f2tf(p_r[j].w);
        }
#pragma unroll
        for (int j = 0; j < 2; j++) {
            const int idx = tid * 2 + j;
            const int r = idx >> 4, c4 = idx & 15;
            uint4 u = {f2tf(v_r[j].x), f2tf(v_r[j].y),
                       f2tf(v_r[j].z), f2tf(v_r[j].w)};
            *reinterpret_cast<uint4*>(&Bs[r][c4 * 4]) = u;
        }
    };

    float acc[2][4][4];
#pragma unroll
    for (int i = 0; i < 2; i++)
#pragma unroll
        for (int j = 0; j < 4; j++)
#pragma unroll
            for (int r = 0; r < 4; r++) acc[i][j][r] = 0.0f;

    ldg_tiles(0);
    for (int k0 = 0; k0 < NN; k0 += 32) {
        sts_tiles();
        __syncthreads();
        if (k0 + 32 < NN) ldg_tiles(k0 + 32);

#pragma unroll
        for (int kk = 0; kk < 32; kk += 8) {
            unsigned a[2][4], bfr[4][2];
#pragma unroll
            for (int i = 0; i < 2; i++) {
                const int mm = wr * 32 + i * 16;
                a[i][0] = As[kk + t][mm + g];
                a[i][1] = As[kk + t][mm + g + 8];
                a[i][2] = As[kk + t + 4][mm + g];
                a[i][3] = As[kk + t + 4][mm + g + 8];
            }
#pragma unroll
            for (int j = 0; j < 4; j++) {
                const int dd = wc * 32 + j * 8;
                bfr[j][0] = Bs[kk + t][dd + g];
                bfr[j][1] = Bs[kk + t + 4][dd + g];
            }
#pragma unroll
            for (int i = 0; i < 2; i++)
#pragma unroll
                for (int j = 0; j < 4; j++)
                    mma_tf32(acc[i][j], a[i][0], a[i][1], a[i][2], a[i][3],
                             bfr[j][0], bfr[j][1]);
        }
        __syncthreads();
    }

#pragma unroll
    for (int j = 0; j < 4; j++) {
        const int col = h * DD + wc * 32 + j * 8 + t * 2;
#pragma unroll
        for (int i = 0; i < 2; i++) {
            const int r0 = n0 + wr * 32 + i * 16;
            float2 o0 = {acc[i][j][0], acc[i][j][1]};
            float2 o1 = {acc[i][j][2], acc[i][j][3]};
            *reinterpret_cast<float2*>(
                &ctx[((size_t)b * NN + r0 + g) * CC + col]) = o0;
            *reinterpret_cast<float2*>(
                &ctx[((size_t)b * NN + r0 + g + 8) * CC + col]) = o1;
        }
    }
}

// ---------------------------------------------------------------------------
extern "C" void kernel_launch(void* const* d_in, const int* in_sizes, int n_in,
                              void* d_out, int out_size)
{
    (void)in_sizes; (void)n_in; (void)out_size;
    const float* x      = (const float*)d_in[0];
    const float* w_qkv  = (const float*)d_in[1];
    const float* b_qkv  = (const float*)d_in[2];
    const float* w_proj = (const float*)d_in[3];
    const float* b_proj = (const float*)d_in[4];

    float* out  = (float*)d_out;
    float* attn = out + (size_t)BB * NN * CC;

    float* qkvp = nullptr;
    float* ctxp = nullptr;
    cudaGetSymbolAddress((void**)&qkvp, g_qkv);
    cudaGetSymbolAddress((void**)&ctxp, g_ctx);

    // 1) QKV projection (tf32 TC, pipelined)
    sgemm_bias_tc<<<dim3(3 * CC / 128, BB * NN / 128), 256>>>(
        x, w_qkv, b_qkv, qkvp, BB * NN, 3 * CC, CC);

    // 2) Fused QK^T + softmax -> attn (single write)
    qk_softmax_fused<<<dim3(NN / FROWS, BB * HH), 512>>>(qkvp, attn);

    // 3) attn @ V (tf32 TC, pipelined)
    av_ctx_tc<<<dim3(NN / 128, BB * HH), 256>>>(attn, qkvp, ctxp);

    // 4) Output projection (tf32 TC, pipelined)
    sgemm_bias_tc<<<dim3(CC / 128, BB * NN / 128), 256>>>(
        ctxp, w_proj, b_proj, out, BB * NN, CC, CC);
}